// round 6
// baseline (speedup 1.0000x reference)
#include <cuda_runtime.h>
#include <cstdint>

// OcrEmbedding: out[b,t,:] = sum_{s=0..3, id!=0} table[id[b,t,s], :]
// B=32, T=512, S=4, D=256, V=50000.
// d_in[0] = subtoken_ids (int32), d_in[1] = table (float32). Output fp32.
//
// Spatial hybrid: CTAs [0,128) gather via double-buffered TMA bulk copies
// (separate in-flight budget from the L1tex LDG queue); CTAs [128,3200)
// run the plain LDG scheme. No cross-path synchronization.

#define BT        (32 * 512)  // 16384 token rows
#define D4        64
#define ROW_BYTES 1024

#define TMA_CTAS       128
#define ROWS_PER_TCTA  32     // 128*32 = 4096 rows via TMA
#define RPS            4      // rows per pipeline stage
#define NITER          (ROWS_PER_TCTA / RPS)   // 8
#define TMA_ROWS       (TMA_CTAS * ROWS_PER_TCTA)

#define LDG_RPC        4      // rows per LDG CTA (R1 scheme)
#define THREADS        256

__device__ __forceinline__ uint32_t smem_u32(const void* p) {
    uint32_t a;
    asm("{ .reg .u64 t; cvta.to.shared.u64 t, %1; cvt.u32.u64 %0, t; }"
        : "=r"(a) : "l"(p));
    return a;
}

__device__ __forceinline__ void mbar_wait(uint32_t mbar_a, uint32_t parity) {
    uint32_t done;
    asm volatile(
        "{\n\t.reg .pred p;\n\t"
        "mbarrier.try_wait.parity.acquire.cta.shared::cta.b64 p, [%1], %2;\n\t"
        "selp.b32 %0, 1, 0, p;\n\t}"
        : "=r"(done) : "r"(mbar_a), "r"(parity) : "memory");
    if (!done) {
        asm volatile(
            "{\n\t.reg .pred P1;\n\t"
            "WL_%=:\n\t"
            "mbarrier.try_wait.parity.acquire.cta.shared::cta.b64 P1, [%0], %1, 0x989680;\n\t"
            "@P1 bra.uni WD_%=;\n\t"
            "bra.uni WL_%=;\n\t"
            "WD_%=:\n\t}"
            :: "r"(mbar_a), "r"(parity) : "memory");
    }
}

__global__ __launch_bounds__(THREADS) void ocr_embed_spatial_kernel(
    const int* __restrict__ ids,          // [BT*4]
    const float* __restrict__ table,      // [V*256]
    float4* __restrict__ out)             // [BT, D4]
{
    extern __shared__ float4 dynbuf[];    // TMA path: 2 stages * 4 rows * 4 ids * 64 f4 = 32KB

    const int tid = threadIdx.x;

    if (blockIdx.x >= TMA_CTAS) {
        // ================= LDG path (R1 scheme) =================
        const int row0 = TMA_ROWS + (blockIdx.x - TMA_CTAS) * LDG_RPC;
        const int q    = tid & 63;
        const int row  = row0 + (tid >> 6);

        int4 id = __ldg((const int4*)(ids + row * 4));

        float4 acc = make_float4(0.f, 0.f, 0.f, 0.f);
        if (id.x != 0) {
            float4 v = __ldg((const float4*)(table + (size_t)id.x * 256) + q);
            acc.x += v.x; acc.y += v.y; acc.z += v.z; acc.w += v.w;
        }
        if (id.y != 0) {
            float4 v = __ldg((const float4*)(table + (size_t)id.y * 256) + q);
            acc.x += v.x; acc.y += v.y; acc.z += v.z; acc.w += v.w;
        }
        if (id.z != 0) {
            float4 v = __ldg((const float4*)(table + (size_t)id.z * 256) + q);
            acc.x += v.x; acc.y += v.y; acc.z += v.z; acc.w += v.w;
        }
        if (id.w != 0) {
            float4 v = __ldg((const float4*)(table + (size_t)id.w * 256) + q);
            acc.x += v.x; acc.y += v.y; acc.z += v.z; acc.w += v.w;
        }
        __stcs(&out[(size_t)row * D4 + q], acc);
        return;
    }

    // ================= TMA path =================
    __shared__ __align__(8) uint64_t mbar[2];

    const int row0 = blockIdx.x * ROWS_PER_TCTA;
    const uint32_t mb0 = smem_u32(&mbar[0]);
    const uint32_t mb1 = smem_u32(&mbar[1]);

    if (tid == 0) {
        asm volatile("mbarrier.init.shared.b64 [%0], 16;" :: "r"(mb0) : "memory");
        asm volatile("mbarrier.init.shared.b64 [%0], 16;" :: "r"(mb1) : "memory");
    }
    __syncthreads();

    // Issue helper: stage slot = iter & 1. 16 threads, one 1KB copy each.
    auto issue = [&](int iter) {
        if (tid < RPS * 4) {
            int r  = iter * RPS + (tid >> 2);
            int s  = tid & 3;
            int id = __ldg(&ids[(row0 + r) * 4 + s]);
            uint32_t mb = (iter & 1) ? mb1 : mb0;
            uint32_t tx = (id != 0) ? ROW_BYTES : 0u;
            asm volatile("mbarrier.arrive.expect_tx.shared.b64 _, [%0], %1;"
                         :: "r"(mb), "r"(tx) : "memory");
            if (id != 0) {
                const float* src = table + (size_t)id * 256;
                uint32_t dst = smem_u32(&dynbuf[((iter & 1) * 16 + tid) * D4]);
                asm volatile(
                    "cp.async.bulk.shared::cta.global.mbarrier::complete_tx::bytes "
                    "[%0], [%1], %2, [%3];"
                    :: "r"(dst), "l"(src), "n"(ROW_BYTES), "r"(mb) : "memory");
            }
        }
    };

    issue(0);
    issue(1);

    for (int i = 0; i < NITER; i++) {
        uint32_t mb = (i & 1) ? mb1 : mb0;
        mbar_wait(mb, (i >> 1) & 1);

        // Sum: 4 rows * 64 chunks = 256 chunks, one per thread.
        {
            int rloc = tid >> 6;              // 0..3
            int q    = tid & 63;
            int row  = row0 + i * RPS + rloc;
            int4 id  = __ldg((const int4*)(ids + row * 4));

            const float4* p = &dynbuf[((i & 1) * 16 + rloc * 4) * D4 + q];
            float4 s = make_float4(0.f, 0.f, 0.f, 0.f);
            if (id.x != 0) { float4 v = p[0];      s.x += v.x; s.y += v.y; s.z += v.z; s.w += v.w; }
            if (id.y != 0) { float4 v = p[D4];     s.x += v.x; s.y += v.y; s.z += v.z; s.w += v.w; }
            if (id.z != 0) { float4 v = p[2 * D4]; s.x += v.x; s.y += v.y; s.z += v.z; s.w += v.w; }
            if (id.w != 0) { float4 v = p[3 * D4]; s.x += v.x; s.y += v.y; s.z += v.z; s.w += v.w; }

            __stcs(&out[(size_t)row * D4 + q], s);
        }
        __syncthreads();            // buffer fully consumed before reissue
        if (i + 2 < NITER) issue(i + 2);
    }
}

extern "C" void kernel_launch(void* const* d_in, const int* in_sizes, int n_in,
                              void* d_out, int out_size)
{
    const int*   ids   = (const int*)d_in[0];
    const float* table = (const float*)d_in[1];
    float4*      out   = (float4*)d_out;

    const int smem = 2 * 16 * D4 * sizeof(float4);   // 32 KB

    static bool attr_set = false;
    if (!attr_set) {
        cudaFuncSetAttribute(ocr_embed_spatial_kernel,
                             cudaFuncAttributeMaxDynamicSharedMemorySize, smem);
        attr_set = true;
    }

    const int ldg_ctas = (BT - TMA_ROWS) / LDG_RPC;  // 3072
    const int blocks   = TMA_CTAS + ldg_ctas;        // 3200

    ocr_embed_spatial_kernel<<<blocks, THREADS, smem>>>(ids, table, out);
}

// round 7
// speedup vs baseline: 1.1662x; 1.1662x over previous
#include <cuda_runtime.h>
#include <cstdint>

// OcrEmbedding: out[b,t,:] = sum_{s=0..3, id!=0} table[id[b,t,s], :]
// B=32, T=512, S=4, D=256, V=50000.
// d_in[0] = subtoken_ids (int32, B*T*S), d_in[1] = table (float32, V*D)
// Output: float32, B*T*D.
//
// Single-wave persistent kernel: 1024 CTAs x 256 threads (~55 warps/SM, one
// wave, no wave transitions). Each CTA owns 16 rows in 4 passes of 4 rows
// (64 threads per row). Subtoken ids for pass p+1 are prefetched during
// pass p, hiding the id->table L2 dependency chain. Table reads evict-first
// (.cs) since random 1KB rows have zero L1 reuse; stores evict-first too.

#define BT      (32 * 512)   // 16384 token rows
#define D4      64
#define CTAS    1024
#define RPC     16           // rows per CTA
#define PASSES  4            // 4 rows per pass (64 threads/row)
#define THREADS 256

__global__ __launch_bounds__(THREADS) void ocr_embed_persist_kernel(
    const int* __restrict__ ids,          // [BT*4]
    const float* __restrict__ table,      // [V*256]
    float4* __restrict__ out)             // [BT, D4]
{
    const int tid  = threadIdx.x;
    const int q    = tid & 63;            // float4 chunk within D
    const int rsub = tid >> 6;            // 0..3: row within pass
    const int row0 = blockIdx.x * RPC;

    int row  = row0 + rsub;
    int4 id  = __ldg((const int4*)(ids + row * 4));   // pass-0 ids

    #pragma unroll
    for (int p = 0; p < PASSES; p++) {
        // Prefetch next pass's ids early; independent of this pass's loads.
        int4 idn;
        const int rown = row + 4;
        if (p + 1 < PASSES) {
            idn = __ldg((const int4*)(ids + rown * 4));
        }

        // Issue all 4 table loads before any consumption (MLP=4/thread,
        // 4 rows in flight per warp-pair across the CTA).
        float4 v0 = make_float4(0.f, 0.f, 0.f, 0.f);
        float4 v1 = v0, v2 = v0, v3 = v0;
        if (id.x != 0) v0 = __ldcs((const float4*)(table + (size_t)id.x * 256) + q);
        if (id.y != 0) v1 = __ldcs((const float4*)(table + (size_t)id.y * 256) + q);
        if (id.z != 0) v2 = __ldcs((const float4*)(table + (size_t)id.z * 256) + q);
        if (id.w != 0) v3 = __ldcs((const float4*)(table + (size_t)id.w * 256) + q);

        float4 s;
        s.x = (v0.x + v1.x) + (v2.x + v3.x);
        s.y = (v0.y + v1.y) + (v2.y + v3.y);
        s.z = (v0.z + v1.z) + (v2.z + v3.z);
        s.w = (v0.w + v1.w) + (v2.w + v3.w);

        __stcs(&out[(size_t)row * D4 + q], s);

        row = rown;
        id  = idn;
    }
}

extern "C" void kernel_launch(void* const* d_in, const int* in_sizes, int n_in,
                              void* d_out, int out_size)
{
    const int*   ids   = (const int*)d_in[0];
    const float* table = (const float*)d_in[1];
    float4*      out   = (float4*)d_out;

    ocr_embed_persist_kernel<<<CTAS, THREADS>>>(ids, table, out);
}

// round 8
// speedup vs baseline: 1.1696x; 1.0029x over previous
#include <cuda_runtime.h>
#include <cstdint>

// OcrEmbedding: out[b,t,:] = sum_{s=0..3, id!=0} table[id[b,t,s], :]
// B=32, T=512, S=4, D=256, V=50000.
// d_in[0] = subtoken_ids (int32, B*T*S), d_in[1] = table (float32, V*D)
// Output: float32, B*T*D.
//
// R1 champion shape (4096 CTAs x 256 thr, 64 thr/row) + L2 residency hints:
//   - table reads: ld.global.nc.L2::cache_hint with evict_last policy
//     (the same 37MB of table rows is re-read every graph replay; pin it)
//   - output stores: __stcs (evict-first; never re-read)
// Model: kernel is LTS-bound (~7.9 TB/s random-gather ceiling); this attacks
// the residual DRAM refills between replays.

#define BT   (32 * 512)   // 16384 token rows
#define D4   64           // float4 chunks per row

__device__ __forceinline__ float4 ldg_evict_last(const float4* p, uint64_t pol) {
    float4 v;
    asm volatile("ld.global.nc.L2::cache_hint.v4.f32 {%0,%1,%2,%3}, [%4], %5;"
                 : "=f"(v.x), "=f"(v.y), "=f"(v.z), "=f"(v.w)
                 : "l"(p), "l"(pol));
    return v;
}

__global__ __launch_bounds__(256) void ocr_embed_kernel(
    const int* __restrict__ ids,          // [BT*4]
    const float* __restrict__ table,      // [V*256]
    float4* __restrict__ out)             // [BT, D4]
{
    const int gid = blockIdx.x * blockDim.x + threadIdx.x;
    const int row = gid >> 6;             // token index
    const int q   = gid & 63;             // float4 chunk within D

    // L2 policy: keep table lines resident across graph replays.
    uint64_t pol;
    asm volatile("createpolicy.fractional.L2::evict_last.b64 %0, 1.0;" : "=l"(pol));

    int4 id = __ldg((const int4*)(ids + row * 4));

    float4 acc = make_float4(0.f, 0.f, 0.f, 0.f);

    if (id.x != 0) {
        float4 v = ldg_evict_last((const float4*)(table + (size_t)id.x * 256) + q, pol);
        acc.x += v.x; acc.y += v.y; acc.z += v.z; acc.w += v.w;
    }
    if (id.y != 0) {
        float4 v = ldg_evict_last((const float4*)(table + (size_t)id.y * 256) + q, pol);
        acc.x += v.x; acc.y += v.y; acc.z += v.z; acc.w += v.w;
    }
    if (id.z != 0) {
        float4 v = ldg_evict_last((const float4*)(table + (size_t)id.z * 256) + q, pol);
        acc.x += v.x; acc.y += v.y; acc.z += v.z; acc.w += v.w;
    }
    if (id.w != 0) {
        float4 v = ldg_evict_last((const float4*)(table + (size_t)id.w * 256) + q, pol);
        acc.x += v.x; acc.y += v.y; acc.z += v.z; acc.w += v.w;
    }

    __stcs(&out[(size_t)row * D4 + q], acc);   // evict-first: never re-read
}

extern "C" void kernel_launch(void* const* d_in, const int* in_sizes, int n_in,
                              void* d_out, int out_size)
{
    const int*   ids   = (const int*)d_in[0];
    const float* table = (const float*)d_in[1];
    float4*      out   = (float4*)d_out;

    const int total   = BT * 64;          // one thread per float4 chunk
    const int threads = 256;
    const int blocks  = total / threads;  // 4096

    ocr_embed_kernel<<<blocks, threads>>>(ids, table, out);
}